// round 9
// baseline (speedup 1.0000x reference)
#include <cuda_runtime.h>
#include <math.h>

#define L 512
#define NCON 20
#define INV_TEMP (1.0f / 0.07f)
#define MAXROWS 32768
#define RP_BLOCKS 592   // 4 blocks/SM on 148 SMs
#define RP_THREADS 256

// scratch (device globals; no allocation allowed)
__device__ float g_t0[MAXROWS];         // per-row complete sz term: log(den0) - d0*invn/tau
__device__ float g_t1[MAXROWS];         // per-row complete nsz term

// ---------------------------------------------------------------------------
// Kernel 1 (identical to R6's proven rowpass): grid-stride over rows of hg
// (L2-resident across replays). Each block builds ebar_sz/ebar_nsz in smem
// from 10 L2-hot concept rows (overlapped across 592 blocks). Per row, lanes
// 0..19 also load the 20 corr values (coalesced 80B) and compute the two
// masked exp-sum denominators on the idle MUFU pipe. Writes COMPLETE per-row
// loss terms t0/t1.
// ---------------------------------------------------------------------------
__global__ void __launch_bounds__(RP_THREADS)
rowpass_kernel(const float* __restrict__ hg, int nrows,
               const float* __restrict__ corr,
               const float* __restrict__ all_emb,
               const int* __restrict__ Psz, int nPsz,
               const int* __restrict__ Pnsz, int nPnsz) {
    __shared__ float se0[L];
    __shared__ float se1[L];
    __shared__ int sp[2][16];
    int tid = threadIdx.x;

    if (tid < nPsz)                    sp[0][tid]      = Psz[tid];
    if (tid >= 32 && tid - 32 < nPnsz) sp[1][tid - 32] = Pnsz[tid - 32];
    __syncthreads();

    // exclusion bitmasks (uniform per warp; computed from smem, cheap)
    unsigned int mask0 = 0u, mask1 = 0u;
    for (int j = 0; j < nPsz; j++)  mask0 |= 1u << sp[0][j];
    for (int j = 0; j < nPnsz; j++) mask1 |= 1u << sp[1][j];

    // build ebar into smem
    for (int t = tid; t < L; t += RP_THREADS) {
        float s0 = 0.0f, s1 = 0.0f;
        for (int j = 0; j < nPsz; j++)  s0 += all_emb[sp[0][j] * L + t];
        for (int j = 0; j < nPnsz; j++) s1 += all_emb[sp[1][j] * L + t];
        se0[t] = s0 / (float)nPsz;
        se1[t] = s1 / (float)nPnsz;
    }
    __syncthreads();

    int wg   = (blockIdx.x * RP_THREADS + tid) >> 5;   // global warp id
    int lane = tid & 31;
    int nwarps = (gridDim.x * RP_THREADS) >> 5;
    const float4* e0p = reinterpret_cast<const float4*>(se0);
    const float4* e1p = reinterpret_cast<const float4*>(se1);
    bool active = lane < NCON;
    float w0m = (active && !((mask0 >> lane) & 1u)) ? 1.0f : 0.0f;
    float w1m = (active && !((mask1 >> lane) & 1u)) ? 1.0f : 0.0f;

    for (int row = wg; row < nrows; row += nwarps) {
        // denominators: lanes 0..19 each handle one concept
        float e = active ? __expf(corr[row * NCON + lane] * INV_TEMP) : 0.0f;
        float den0 = e * w0m;
        float den1 = e * w1m;

        const float4* rp = reinterpret_cast<const float4*>(hg + (size_t)row * L);
        float ss = 0.0f, d0 = 0.0f, d1 = 0.0f;
#pragma unroll
        for (int it = 0; it < 4; it++) {
            int idx = it * 32 + lane;
            float4 v  = rp[idx];
            float4 e0 = e0p[idx];
            float4 e1 = e1p[idx];
            ss = fmaf(v.x, v.x, fmaf(v.y, v.y, fmaf(v.z, v.z, fmaf(v.w, v.w, ss))));
            d0 = fmaf(v.x, e0.x, fmaf(v.y, e0.y, fmaf(v.z, e0.z, fmaf(v.w, e0.w, d0))));
            d1 = fmaf(v.x, e1.x, fmaf(v.y, e1.y, fmaf(v.z, e1.z, fmaf(v.w, e1.w, d1))));
        }
#pragma unroll
        for (int o = 16; o > 0; o >>= 1) {
            ss   += __shfl_xor_sync(0xffffffffu, ss, o);
            d0   += __shfl_xor_sync(0xffffffffu, d0, o);
            d1   += __shfl_xor_sync(0xffffffffu, d1, o);
            den0 += __shfl_xor_sync(0xffffffffu, den0, o);
            den1 += __shfl_xor_sync(0xffffffffu, den1, o);
        }
        if (lane == 0) {
            float invn = 1.0f / fmaxf(sqrtf(ss), 1e-12f);
            g_t0[row] = __logf(den0) - d0 * invn * INV_TEMP;
            g_t1[row] = __logf(den1) - d1 * invn * INV_TEMP;
        }
    }
}

// ---------------------------------------------------------------------------
// Kernel 2: single-block gather-sum. 1024 threads x 32 samples each = 32768.
// Per thread: 32 INDEPENDENT idx->t chains (MLP=32; idx coalesced, t arrays
// are 256 KB and L2-hot from kernel 1). Fixed per-thread accumulation order +
// fixed tree -> deterministic. No atomics, no cross-block sync; writes out[0].
// ---------------------------------------------------------------------------
__global__ void __launch_bounds__(1024)
gather_kernel(const int* __restrict__ sz_idx, int Ns,
              const int* __restrict__ nsz_idx, int Nn,
              float invNs, float invNn, float* __restrict__ out) {
    int tid = threadIdx.x;
    int total = Ns + Nn;

    float acc = 0.0f;
    for (int i = tid; i < total; i += 1024) {
        int branch = (i >= Ns);
        int j = branch ? (i - Ns) : i;
        int r = branch ? nsz_idx[j] : sz_idx[j];
        float t = branch ? g_t1[r] : g_t0[r];
        acc += t * (branch ? invNn : invNs);
    }

    __shared__ float sh[1024];
    sh[tid] = acc;
    __syncthreads();
    for (int s = 512; s > 0; s >>= 1) {
        if (tid < s) sh[tid] += sh[tid + s];
        __syncthreads();
    }
    if (tid == 0) out[0] = sh[0];
}

extern "C" void kernel_launch(void* const* d_in, const int* in_sizes, int n_in,
                              void* d_out, int out_size) {
    const float* hg       = (const float*)d_in[0];
    const float* corr     = (const float*)d_in[1];
    const float* all_emb  = (const float*)d_in[2];
    const int*   sz_idx   = (const int*)d_in[3];
    const int*   nsz_idx  = (const int*)d_in[4];
    const int*   Psz_idx  = (const int*)d_in[5];
    const int*   Pnsz_idx = (const int*)d_in[6];
    float* out = (float*)d_out;

    int nrows = in_sizes[0] / L;          // 32768
    int Ns    = in_sizes[3];
    int Nn    = in_sizes[4];
    int nPsz  = in_sizes[5];
    int nPnsz = in_sizes[6];

    rowpass_kernel<<<RP_BLOCKS, RP_THREADS>>>(hg, nrows, corr, all_emb,
                                              Psz_idx, nPsz, Pnsz_idx, nPnsz);

    gather_kernel<<<1, 1024>>>(sz_idx, Ns, nsz_idx, Nn,
                               1.0f / (float)Ns, 1.0f / (float)Nn, out);
}

// round 10
// speedup vs baseline: 1.5821x; 1.5821x over previous
#include <cuda_runtime.h>
#include <math.h>

#define L 512
#define NCON 20
#define INV_TEMP (1.0f / 0.07f)
#define SD_BLOCKS 592   // 4 blocks/SM on 148 SMs; all co-resident
#define SD_THREADS 256
#define WPB (SD_THREADS / 32)

// scratch (device globals; no allocation allowed)
__device__ float g_pB[SD_BLOCKS];        // per-block partials
__device__ unsigned int g_fin = 0;       // finalize counter (reset by last block)

// ---------------------------------------------------------------------------
// Single sample-driven kernel. Blocks [0,Bs) handle sz samples, [Bs,grid)
// handle nsz samples (branch uniform per block -> ONE ebar + ONE mask per
// block, minimal registers). One warp per sample, grid-stride over samples:
//   term_i = (log den_i - <row, ebar> * invnorm / tau) / Nbranch
// Row reads are coalesced (warp reads whole 2KB row); duplicate rows across
// samples hit L2. Deterministic: fixed per-warp sample sets, fixed-tree block
// reduction, fixed-order last-block finalize.
// ---------------------------------------------------------------------------
__global__ void __launch_bounds__(SD_THREADS)
sample_kernel(const float* __restrict__ hg,
              const float* __restrict__ corr,
              const float* __restrict__ all_emb,
              const int* __restrict__ Psz, int nPsz,
              const int* __restrict__ Pnsz, int nPnsz,
              const int* __restrict__ sz_idx, int Ns,
              const int* __restrict__ nsz_idx, int Nn,
              int Bs, float invNs, float invNn,
              float* __restrict__ out) {
    __shared__ float se[L];
    __shared__ int sp[16];
    __shared__ float sw[WPB];
    __shared__ float sh[SD_THREADS];
    __shared__ bool is_last;

    int tid = threadIdx.x;
    int branch = (blockIdx.x >= Bs) ? 1 : 0;
    const int* P = branch ? Pnsz : Psz;
    int nP = branch ? nPnsz : nPsz;
    const int* idxp = branch ? nsz_idx : sz_idx;
    int count = branch ? Nn : Ns;
    float scale = branch ? invNn : invNs;

    if (tid < nP) sp[tid] = P[tid];
    __syncthreads();

    // exclusion bitmask for this branch (uniform)
    unsigned int mask = 0u;
    for (int j = 0; j < nP; j++) mask |= 1u << sp[j];

    // build this branch's ebar into smem (nP L2-hot concept rows)
    for (int t = tid; t < L; t += SD_THREADS) {
        float s = 0.0f;
        for (int j = 0; j < nP; j++) s += all_emb[sp[j] * L + t];
        se[t] = s / (float)nP;
    }
    __syncthreads();

    int lane = tid & 31;
    int wib  = tid >> 5;
    // warp index within this branch's block range, and branch warp count
    int bb = branch ? (blockIdx.x - Bs) : blockIdx.x;
    int nbb = branch ? (gridDim.x - Bs) : Bs;
    int wg = bb * WPB + wib;
    int nw = nbb * WPB;

    const float4* ep = reinterpret_cast<const float4*>(se);
    bool act = lane < NCON;
    float wm = (act && !((mask >> lane) & 1u)) ? 1.0f : 0.0f;

    float acc = 0.0f;
    for (int i = wg; i < count; i += nw) {
        int r = idxp[i];  // same address per warp -> broadcast load

        // denominator: lanes 0..19 handle one concept each
        float e = act ? __expf(corr[r * NCON + lane] * INV_TEMP) : 0.0f;
        float den = e * wm;

        const float4* rp = reinterpret_cast<const float4*>(hg + (size_t)r * L);
        float ss = 0.0f, d = 0.0f;
#pragma unroll
        for (int it = 0; it < 4; it++) {
            int idx = it * 32 + lane;
            float4 v  = rp[idx];
            float4 ev = ep[idx];
            ss = fmaf(v.x, v.x, fmaf(v.y, v.y, fmaf(v.z, v.z, fmaf(v.w, v.w, ss))));
            d  = fmaf(v.x, ev.x, fmaf(v.y, ev.y, fmaf(v.z, ev.z, fmaf(v.w, ev.w, d))));
        }
#pragma unroll
        for (int o = 16; o > 0; o >>= 1) {
            ss  += __shfl_xor_sync(0xffffffffu, ss, o);
            d   += __shfl_xor_sync(0xffffffffu, d, o);
            den += __shfl_xor_sync(0xffffffffu, den, o);
        }
        if (lane == 0) {
            float invn = 1.0f / fmaxf(sqrtf(ss), 1e-12f);
            acc += (__logf(den) - d * invn * INV_TEMP) * scale;
        }
    }

    // block partial + last-block fixed-order finalize
    if (lane == 0) sw[wib] = acc;
    __syncthreads();
    if (tid == 0) {
        float s = 0.0f;
#pragma unroll
        for (int k = 0; k < WPB; k++) s += sw[k];
        g_pB[blockIdx.x] = s;
        __threadfence();
        is_last = (atomicAdd(&g_fin, 1u) == gridDim.x - 1);
    }
    __syncthreads();

    if (is_last) {
        __threadfence();  // see all blocks' partials
        float a = 0.0f;
        for (int j = tid; j < SD_BLOCKS; j += SD_THREADS) a += g_pB[j];  // fixed order
        sh[tid] = a;
        __syncthreads();
        for (int s = 128; s > 0; s >>= 1) {
            if (tid < s) sh[tid] += sh[tid + s];
            __syncthreads();
        }
        if (tid == 0) { out[0] = sh[0]; g_fin = 0u; }
    }
}

extern "C" void kernel_launch(void* const* d_in, const int* in_sizes, int n_in,
                              void* d_out, int out_size) {
    const float* hg       = (const float*)d_in[0];
    const float* corr     = (const float*)d_in[1];
    const float* all_emb  = (const float*)d_in[2];
    const int*   sz_idx   = (const int*)d_in[3];
    const int*   nsz_idx  = (const int*)d_in[4];
    const int*   Psz_idx  = (const int*)d_in[5];
    const int*   Pnsz_idx = (const int*)d_in[6];
    float* out = (float*)d_out;

    int Ns    = in_sizes[3];
    int Nn    = in_sizes[4];
    int nPsz  = in_sizes[5];
    int nPnsz = in_sizes[6];

    // split blocks proportionally between branches
    long long tot = (long long)Ns + (long long)Nn;
    int Bs = (int)(((long long)SD_BLOCKS * Ns + tot - 1) / tot);
    if (Bs < 1) Bs = 1;
    if (Bs > SD_BLOCKS - 1) Bs = SD_BLOCKS - 1;

    sample_kernel<<<SD_BLOCKS, SD_THREADS>>>(hg, corr, all_emb,
                                             Psz_idx, nPsz, Pnsz_idx, nPnsz,
                                             sz_idx, Ns, nsz_idx, Nn,
                                             Bs, 1.0f / (float)Ns, 1.0f / (float)Nn,
                                             out);
}